// round 1
// baseline (speedup 1.0000x reference)
#include <cuda_runtime.h>
#include <math.h>

// ---------------------------------------------------------------------------
// BlindSpotBlock: shifted-window blind-spot attention + proj + MLP
// B=8 H=256 W=256 C=96, WS=8 SS=4 NH=6 CH=16, NP=64, NW=1024, B*NW=8192
// ---------------------------------------------------------------------------

#define NPIX   (8*256*256)         // 524288 pixels
#define CDIM   96

// Intermediate X = attention-half output, (B,H,W,C) fp32
__device__ float g_X[NPIX * CDIM];

// ---- Kernel A: shift+window attention + bias + mask + softmax + AV + q-res
//      + LayerNorm + proj(96x96) + window-reverse+unshift scatter into g_X ---
// Shared memory layout (floats):
//   k_s   [0,      6144)   64x96 K tile
//   v_s   [6144,  12288)   64x96 V tile
//   w_s   [0,      9216)   projW^T, reused over k_s/v_s after attention
//   out_s [12288, 18496)   64x97 (padded) attention output / normalized
//   rpb_s [18496, 19846)   225x6 relative position bias table
//   base_s[19846, 19910)   per-patch global element offsets (int)
//   reg_s [19910, 19974)   per-patch mask region id (int)
#define A_SMEM_FLOATS 19974

__global__ void __launch_bounds__(384, 1)
attn_proj_kernel(const float* __restrict__ q_in,
                 const float* __restrict__ k_in,
                 const float* __restrict__ v_in,
                 const float* __restrict__ rpb,
                 const float* __restrict__ ng,
                 const float* __restrict__ nb,
                 const float* __restrict__ pw,
                 const float* __restrict__ pb)
{
    extern __shared__ float sm[];
    float* k_s    = sm;
    float* v_s    = sm + 6144;
    float* w_s    = sm;                 // reuse after attention phase
    float* out_s  = sm + 12288;         // stride 97
    float* rpb_s  = sm + 18496;
    int*   base_s = (int*)(sm + 19846);
    int*   reg_s  = (int*)(sm + 19910);

    const int tid  = threadIdx.x;
    const int w    = blockIdx.x;        // 0..8191
    const int b    = w >> 10;
    const int widx = w & 1023;
    const int wy   = widx >> 5;
    const int wx   = widx & 31;

    // per-patch base offsets (roll(-SS) folded in) + mask regions
    if (tid < 64) {
        const int py = tid >> 3, px = tid & 7;
        const int ys = (wy * 8 + py + 4) & 255;
        const int xs = (wx * 8 + px + 4) & 255;
        base_s[tid] = ((b * 256 + ys) * 256 + xs) * 96;
        const int row = wy * 8 + py, col = wx * 8 + px;
        const int rr = (row < 248) ? 0 : ((row < 252) ? 1 : 2);
        const int cr = (col < 248) ? 0 : ((col < 252) ? 1 : 2);
        reg_s[tid] = rr * 3 + cr;
    }
    for (int n = tid; n < 225 * 6; n += 384) rpb_s[n] = rpb[n];
    __syncthreads();

    // gather K/V window tiles (coalesced per-patch 96-float runs)
    {
        const int c  = tid % 96;
        const int p0 = tid / 96;
        for (int p = p0; p < 64; p += 4) {
            const int g = base_s[p] + c;
            k_s[p * 96 + c] = k_in[g];
            v_s[p * 96 + c] = v_in[g];
        }
    }
    __syncthreads();

    // thread = (head, query row)
    const int hh = tid >> 6;            // 0..5
    const int i  = tid & 63;            // 0..63
    const int co = hh * 16;
    const int yi = i >> 3, xi = i & 7;
    const int ri = reg_s[i];

    float qv[16];
    {
        const float* qp = q_in + base_s[i] + co;
#pragma unroll
        for (int c = 0; c < 16; c++) qv[c] = qp[c] * 0.25f;  // CH^-0.5
    }

    // scores (register resident, fully unrolled)
    float sc[64];
    float mx = -3.0e38f;
#pragma unroll
    for (int j = 0; j < 64; j++) {
        const float* kp = k_s + j * 96 + co;
        float s0 = 0.f, s1 = 0.f, s2 = 0.f, s3 = 0.f;
#pragma unroll
        for (int c = 0; c < 16; c += 4) {
            s0 = fmaf(qv[c + 0], kp[c + 0], s0);
            s1 = fmaf(qv[c + 1], kp[c + 1], s1);
            s2 = fmaf(qv[c + 2], kp[c + 2], s2);
            s3 = fmaf(qv[c + 3], kp[c + 3], s3);
        }
        float s = (s0 + s1) + (s2 + s3);
        const int yj = j >> 3, xj = j & 7;
        s += rpb_s[((yi - yj + 7) * 15 + (xi - xj + 7)) * 6 + hh];
        if (j == i || reg_s[j] != ri) s += -1e9f;   // blind spot + shift mask
        sc[j] = s;
        mx = fmaxf(mx, s);
    }

    // unnormalized softmax-weighted AV, divide once at the end
    float acc[16];
#pragma unroll
    for (int c = 0; c < 16; c++) acc[c] = 0.f;
    float ssum = 0.f;
#pragma unroll
    for (int j = 0; j < 64; j++) {
        const float p = __expf(sc[j] - mx);
        ssum += p;
        const float* vp = v_s + j * 96 + co;
#pragma unroll
        for (int c = 0; c < 16; c++) acc[c] = fmaf(p, vp[c], acc[c]);
    }
    const float inv = 1.0f / ssum;
#pragma unroll
    for (int c = 0; c < 16; c++)
        out_s[i * 97 + co + c] = fmaf(acc[c], inv, qv[c]);   // + scaled-q residual
    __syncthreads();

    // LayerNorm (threads 0..63, one row each) || projW^T load (threads 64..383)
    if (tid < 64) {
        float* r = out_s + tid * 97;
        float mu = 0.f;
#pragma unroll 8
        for (int c = 0; c < 96; c++) mu += r[c];
        mu *= (1.0f / 96.0f);
        float var = 0.f;
#pragma unroll 8
        for (int c = 0; c < 96; c++) { const float d = r[c] - mu; var = fmaf(d, d, var); }
        const float rs = rsqrtf(var * (1.0f / 96.0f) + 1e-5f);
#pragma unroll 8
        for (int c = 0; c < 96; c++)
            r[c] = (r[c] - mu) * rs * ng[c] + nb[c];
    } else {
        for (int n = tid - 64; n < 9216; n += 320) {
            const int c = n / 96, k = n - c * 96;
            w_s[k * 96 + c] = pw[n];     // transpose: w_s[k][c_out] = projW[c_out][k]
        }
    }
    __syncthreads();

    // proj GEMM: out_s(64x96) @ w_s(96x96), 4x4 register tile per thread
    {
        const int r0 = (tid & 15) * 4;
        const int c0 = (tid >> 4) * 4;   // 24 col groups
        float a0 = pb[c0 + 0], a1 = pb[c0 + 1], a2 = pb[c0 + 2], a3 = pb[c0 + 3];
        float a4 = a0, a5 = a1, a6 = a2, a7 = a3;
        float a8 = a0, a9 = a1, a10 = a2, a11 = a3;
        float a12 = a0, a13 = a1, a14 = a2, a15 = a3;
#pragma unroll 4
        for (int k = 0; k < 96; k++) {
            const float x0 = out_s[(r0 + 0) * 97 + k];
            const float x1 = out_s[(r0 + 1) * 97 + k];
            const float x2 = out_s[(r0 + 2) * 97 + k];
            const float x3 = out_s[(r0 + 3) * 97 + k];
            const float4 wv = *(const float4*)(w_s + k * 96 + c0);
            a0  = fmaf(x0, wv.x, a0);  a1  = fmaf(x0, wv.y, a1);
            a2  = fmaf(x0, wv.z, a2);  a3  = fmaf(x0, wv.w, a3);
            a4  = fmaf(x1, wv.x, a4);  a5  = fmaf(x1, wv.y, a5);
            a6  = fmaf(x1, wv.z, a6);  a7  = fmaf(x1, wv.w, a7);
            a8  = fmaf(x2, wv.x, a8);  a9  = fmaf(x2, wv.y, a9);
            a10 = fmaf(x2, wv.z, a10); a11 = fmaf(x2, wv.w, a11);
            a12 = fmaf(x3, wv.x, a12); a13 = fmaf(x3, wv.y, a13);
            a14 = fmaf(x3, wv.z, a14); a15 = fmaf(x3, wv.w, a15);
        }
        *(float4*)(g_X + base_s[r0 + 0] + c0) = make_float4(a0, a1, a2, a3);
        *(float4*)(g_X + base_s[r0 + 1] + c0) = make_float4(a4, a5, a6, a7);
        *(float4*)(g_X + base_s[r0 + 2] + c0) = make_float4(a8, a9, a10, a11);
        *(float4*)(g_X + base_s[r0 + 3] + c0) = make_float4(a12, a13, a14, a15);
    }
}

// ---- Kernel B: out = X + fc2(gelu(fc1(LN2(X)))) -------------------------
// Shared memory (floats):
//   w_s  [0,     9216)   weight (transposed), reused for fc1 then fc2
//   x_s  [9216, 15424)   64x97 raw X tile
//   xn_s [15424,21632)   64x97 normalized
//   h_s  [21632,27840)   64x97 hidden
#define B_SMEM_FLOATS 27840

__global__ void __launch_bounds__(256, 1)
mlp_kernel(const float* __restrict__ n2g, const float* __restrict__ n2b,
           const float* __restrict__ w1, const float* __restrict__ b1,
           const float* __restrict__ w2, const float* __restrict__ b2,
           float* __restrict__ out)
{
    extern __shared__ float sm[];
    float* w_s  = sm;
    float* x_s  = sm + 9216;
    float* xn_s = sm + 15424;
    float* h_s  = sm + 21632;

    const int tid = threadIdx.x;
    const size_t p0 = (size_t)blockIdx.x * 64;
    const float* xg = g_X + p0 * 96;

    for (int n = tid; n < 6144; n += 256) {
        const int p = n / 96, c = n - p * 96;
        x_s[p * 97 + c] = xg[n];
    }
    __syncthreads();

    // LN2 (threads 0..63) || fc1W^T load (threads 64..255)
    if (tid < 64) {
        const float* r = x_s + tid * 97;
        float mu = 0.f;
#pragma unroll 8
        for (int c = 0; c < 96; c++) mu += r[c];
        mu *= (1.0f / 96.0f);
        float var = 0.f;
#pragma unroll 8
        for (int c = 0; c < 96; c++) { const float d = r[c] - mu; var = fmaf(d, d, var); }
        const float rs = rsqrtf(var * (1.0f / 96.0f) + 1e-5f);
        float* wr = xn_s + tid * 97;
#pragma unroll 8
        for (int c = 0; c < 96; c++)
            wr[c] = (r[c] - mu) * rs * n2g[c] + n2b[c];
    } else {
        for (int n = tid - 64; n < 9216; n += 192) {
            const int c = n / 96, k = n - c * 96;
            w_s[k * 96 + c] = w1[n];
        }
    }
    __syncthreads();

    const int r0 = (tid & 15) * 4;       // 16 pixel groups x 4
    const int c0 = (tid >> 4) * 6;       // 16 col groups x 6

    // GEMM1: h = gelu(xn @ fc1W^T + b1)
    {
        float a[24];
#pragma unroll
        for (int dc = 0; dc < 6; dc++) {
            const float bb = b1[c0 + dc];
            a[dc] = bb; a[6 + dc] = bb; a[12 + dc] = bb; a[18 + dc] = bb;
        }
#pragma unroll 4
        for (int k = 0; k < 96; k++) {
            const float x0 = xn_s[(r0 + 0) * 97 + k];
            const float x1 = xn_s[(r0 + 1) * 97 + k];
            const float x2 = xn_s[(r0 + 2) * 97 + k];
            const float x3 = xn_s[(r0 + 3) * 97 + k];
            const float* wr = w_s + k * 96 + c0;
#pragma unroll
            for (int dc = 0; dc < 6; dc++) {
                const float wv = wr[dc];
                a[dc]      = fmaf(x0, wv, a[dc]);
                a[6 + dc]  = fmaf(x1, wv, a[6 + dc]);
                a[12 + dc] = fmaf(x2, wv, a[12 + dc]);
                a[18 + dc] = fmaf(x3, wv, a[18 + dc]);
            }
        }
#pragma unroll
        for (int dr = 0; dr < 4; dr++)
#pragma unroll
            for (int dc = 0; dc < 6; dc++) {
                float v = a[dr * 6 + dc];
                v = 0.5f * v * (1.0f + erff(v * 0.70710678118654752440f));
                h_s[(r0 + dr) * 97 + c0 + dc] = v;
            }
    }
    __syncthreads();

    for (int n = tid; n < 9216; n += 256) {
        const int c = n / 96, k = n - c * 96;
        w_s[k * 96 + c] = w2[n];
    }
    __syncthreads();

    // GEMM2 + residual + store
    {
        float a[24];
#pragma unroll
        for (int dc = 0; dc < 6; dc++) {
            const float bb = b2[c0 + dc];
            a[dc] = bb; a[6 + dc] = bb; a[12 + dc] = bb; a[18 + dc] = bb;
        }
#pragma unroll 4
        for (int k = 0; k < 96; k++) {
            const float x0 = h_s[(r0 + 0) * 97 + k];
            const float x1 = h_s[(r0 + 1) * 97 + k];
            const float x2 = h_s[(r0 + 2) * 97 + k];
            const float x3 = h_s[(r0 + 3) * 97 + k];
            const float* wr = w_s + k * 96 + c0;
#pragma unroll
            for (int dc = 0; dc < 6; dc++) {
                const float wv = wr[dc];
                a[dc]      = fmaf(x0, wv, a[dc]);
                a[6 + dc]  = fmaf(x1, wv, a[6 + dc]);
                a[12 + dc] = fmaf(x2, wv, a[12 + dc]);
                a[18 + dc] = fmaf(x3, wv, a[18 + dc]);
            }
        }
#pragma unroll
        for (int dr = 0; dr < 4; dr++)
#pragma unroll
            for (int dc = 0; dc < 6; dc++)
                out[(p0 + r0 + dr) * 96 + c0 + dc] =
                    x_s[(r0 + dr) * 97 + c0 + dc] + a[dr * 6 + dc];
    }
}

// ---------------------------------------------------------------------------
extern "C" void kernel_launch(void* const* d_in, const int* in_sizes, int n_in,
                              void* d_out, int out_size)
{
    const float* q   = (const float*)d_in[0];
    const float* k   = (const float*)d_in[1];
    const float* v   = (const float*)d_in[2];
    const float* rpb = (const float*)d_in[3];
    const float* ng  = (const float*)d_in[4];
    const float* nb  = (const float*)d_in[5];
    const float* pw  = (const float*)d_in[6];
    const float* pb  = (const float*)d_in[7];
    const float* n2g = (const float*)d_in[8];
    const float* n2b = (const float*)d_in[9];
    const float* w1  = (const float*)d_in[10];
    const float* b1  = (const float*)d_in[11];
    const float* w2  = (const float*)d_in[12];
    const float* b2  = (const float*)d_in[13];
    float* out = (float*)d_out;

    cudaFuncSetAttribute(attn_proj_kernel,
                         cudaFuncAttributeMaxDynamicSharedMemorySize,
                         A_SMEM_FLOATS * 4);
    cudaFuncSetAttribute(mlp_kernel,
                         cudaFuncAttributeMaxDynamicSharedMemorySize,
                         B_SMEM_FLOATS * 4);

    attn_proj_kernel<<<8192, 384, A_SMEM_FLOATS * 4>>>(q, k, v, rpb, ng, nb, pw, pb);
    mlp_kernel<<<8192, 256, B_SMEM_FLOATS * 4>>>(n2g, n2b, w1, b1, w2, b2, out);
}